// round 4
// baseline (speedup 1.0000x reference)
// GAT layer: q_ij = adj*max(b_j, r_i*b2_j) built in registers -> HMMA m16n8k16.
#include <cuda_runtime.h>
#include <cuda_fp16.h>
#include <cstdint>

#define NN 4096
#define NH 4
#define OD 64
#define ID 256
#define NCH 256
#define NTL 9

__device__ float  g_h[NN * ID];
__device__ __half g_r[NH * NN], g_b[NH * NN], g_b2[NH * NN];
__device__ uint4  g_adjp[256 * 256 * 32];          // A fragments (32 MB)
__device__ uint2  g_bfrag[NH * NCH * NTL * 32];    // B fragments (2.25 MB)

__device__ __forceinline__ unsigned adj2h(int2 v) {
    __half2 h = __halves2half2(__int2half_rn(v.x > 0), __int2half_rn(v.y > 0));
    return *(unsigned*)&h;
}
__device__ __forceinline__ __half2 u2h(unsigned v) { __half2 h; *(unsigned*)&h = v; return h; }
__device__ __forceinline__ unsigned h2u(__half2 v) { return *(unsigned*)&v; }

__device__ __forceinline__ void mma16816(float* d, unsigned a0, unsigned a1,
                                         unsigned a2, unsigned a3,
                                         unsigned b0, unsigned b1) {
    asm volatile(
        "mma.sync.aligned.m16n8k16.row.col.f32.f16.f16.f32 "
        "{%0,%1,%2,%3},{%4,%5,%6,%7},{%8,%9},{%0,%1,%2,%3};"
        : "+f"(d[0]), "+f"(d[1]), "+f"(d[2]), "+f"(d[3])
        : "r"(a0), "r"(a1), "r"(a2), "r"(a3), "r"(b0), "r"(b1));
}

// K0: adj int32 -> fp16 A-fragment layout. t = ((rowtile*256+chunk)*32+lane)
__global__ void __launch_bounds__(256) k_adjp(const int* __restrict__ adj) {
    int t = blockIdx.x * 256 + threadIdx.x;
    int lane = t & 31, chunk = (t >> 5) & 255, rt = t >> 13;
    int r0 = rt * 16 + (lane >> 2);
    int c = chunk * 16 + (lane & 3) * 2;
    const int2* p = (const int2*)adj;
    int2 v0 = p[((size_t)r0 * NN + c) >> 1];
    int2 v1 = p[((size_t)(r0 + 8) * NN + c) >> 1];
    int2 v2 = p[((size_t)r0 * NN + c + 8) >> 1];
    int2 v3 = p[((size_t)(r0 + 8) * NN + c + 8) >> 1];
    g_adjp[t] = make_uint4(adj2h(v0), adj2h(v1), adj2h(v2), adj2h(v3));
}

// K1: h = x @ W (fp32, 64x64 tiles, 256 threads)
__global__ void __launch_bounds__(256) k_gemm_h(const float* __restrict__ x,
                                                const float* __restrict__ W) {
    __shared__ float As[16][68], Bs[16][68];
    const int t = threadIdx.x;
    const int bm = blockIdx.x * 64, bn = blockIdx.y * 64;
    const int tx = t & 15, ty = t >> 4;
    const float4* x4 = (const float4*)x;
    const float4* W4 = (const float4*)W;
    const int am = t >> 2, ak = t & 3;
    const int bk = t >> 4, bq = t & 15;
    float acc[4][4];
#pragma unroll
    for (int i = 0; i < 4; i++)
#pragma unroll
        for (int j = 0; j < 4; j++) acc[i][j] = 0.f;
    for (int k0 = 0; k0 < ID; k0 += 16) {
        float4 av = x4[(size_t)(bm + am) * (ID / 4) + (k0 >> 2) + ak];
        As[ak * 4 + 0][am] = av.x; As[ak * 4 + 1][am] = av.y;
        As[ak * 4 + 2][am] = av.z; As[ak * 4 + 3][am] = av.w;
        *(float4*)&Bs[bk][bq * 4] = W4[(size_t)(k0 + bk) * (ID / 4) + (bn >> 2) + bq];
        __syncthreads();
#pragma unroll
        for (int kk = 0; kk < 16; kk++) {
            float a[4], b[4];
            *(float4*)a = *(const float4*)&As[kk][ty * 4];
            *(float4*)b = *(const float4*)&Bs[kk][tx * 4];
#pragma unroll
            for (int i = 0; i < 4; i++)
#pragma unroll
                for (int j = 0; j < 4; j++) acc[i][j] += a[i] * b[j];
        }
        __syncthreads();
    }
#pragma unroll
    for (int i = 0; i < 4; i++)
        *(float4*)&g_h[(size_t)(bm + ty * 4 + i) * ID + bn + tx * 4] =
            make_float4(acc[i][0], acc[i][1], acc[i][2], acc[i][3]);
}

// K2a: per-node scores -> exp tables (one warp per node)
__global__ void __launch_bounds__(256) k_etab(const float* __restrict__ att) {
    const int gw = (blockIdx.x * 256 + threadIdx.x) >> 5;
    const int lane = threadIdx.x & 31;
    const float* hr = g_h + (size_t)gw * ID;
#pragma unroll
    for (int h = 0; h < NH; h++) {
        float x0 = hr[h * OD + lane], x1 = hr[h * OD + 32 + lane];
        float s = x0 * att[h * 128 + lane] + x1 * att[h * 128 + 32 + lane];
        float d = x0 * att[h * 128 + 64 + lane] + x1 * att[h * 128 + 96 + lane];
#pragma unroll
        for (int o = 16; o > 0; o >>= 1) {
            s += __shfl_xor_sync(~0u, s, o);
            d += __shfl_xor_sync(~0u, d, o);
        }
        if (lane == 0) {
            g_r [h * NN + gw] = __float2half(expf(-0.8f * s));
            g_b [h * NN + gw] = __float2half(expf(d));
            g_b2[h * NN + gw] = __float2half(expf(0.2f * d));
        }
    }
}

// K2b: B fragments: cols 0..63 = h, col 64 = 1.0 (denominator), 65..71 = 0
__global__ void __launch_bounds__(256) k_bfrag() {
    int t = blockIdx.x * 256 + threadIdx.x;   // NH*NCH*NTL*32 = 294912
    int lane = t & 31, w = t >> 5;
    int nt = w % NTL, chunk = (w / NTL) & 255, head = w / (NTL * 256);
    int k = chunk * 16 + (lane & 3) * 2;
    int n = nt * 8 + (lane >> 2);
    float f0, f1, f2, f3;
    if (n < OD) {
        const float* hp = g_h + head * OD + n;
        f0 = hp[(size_t)k * ID];       f1 = hp[(size_t)(k + 1) * ID];
        f2 = hp[(size_t)(k + 8) * ID]; f3 = hp[(size_t)(k + 9) * ID];
    } else if (n == OD) { f0 = f1 = f2 = f3 = 1.f; }
    else                { f0 = f1 = f2 = f3 = 0.f; }
    __half2 r0 = __floats2half2_rn(f0, f1), r1 = __floats2half2_rn(f2, f3);
    g_bfrag[t] = make_uint2(h2u(r0), h2u(r1));
}

// K3: fused score construction + HMMA + softmax normalize.
// CTA = 32 rows x 4 heads; warp = (head = wid/2, 16-row tile = wid&1). No smem.
__global__ void __launch_bounds__(256, 1) k_attn(float* __restrict__ out) {
    const int tid = threadIdx.x, wid = tid >> 5, lane = tid & 31;
    const int head = wid >> 1;
    const int rt = blockIdx.x * 2 + (wid & 1);
    const int rlo = rt * 16 + (lane >> 2);
    const int c0 = (lane & 3) * 2;

    const __half2 ra = __half2half2(g_r[head * NN + rlo]);
    const __half2 rb = __half2half2(g_r[head * NN + rlo + 8]);
    const uint4* adjp = g_adjp + (size_t)rt * 256 * 32 + lane;
    const uint2* bfr = g_bfrag + (size_t)head * NCH * NTL * 32 + lane;
    const __half* pb = g_b + head * NN + c0;
    const __half* pb2 = g_b2 + head * NN + c0;

    float acc[NTL][4];
#pragma unroll
    for (int i = 0; i < NTL; i++)
#pragma unroll
        for (int j = 0; j < 4; j++) acc[i][j] = 0.f;

#pragma unroll 4
    for (int ch = 0; ch < NCH; ch++) {
        uint4 am = adjp[ch * 32];
        __half2 b01 = *(const __half2*)(pb + ch * 16);
        __half2 b89 = *(const __half2*)(pb + ch * 16 + 8);
        __half2 c01 = *(const __half2*)(pb2 + ch * 16);
        __half2 c89 = *(const __half2*)(pb2 + ch * 16 + 8);
        unsigned qa = h2u(__hmul2(u2h(am.x), __hmax2(b01, __hmul2(ra, c01))));
        unsigned qb = h2u(__hmul2(u2h(am.y), __hmax2(b01, __hmul2(rb, c01))));
        unsigned qc = h2u(__hmul2(u2h(am.z), __hmax2(b89, __hmul2(ra, c89))));
        unsigned qd = h2u(__hmul2(u2h(am.w), __hmax2(b89, __hmul2(rb, c89))));
        const uint2* bp = bfr + ch * NTL * 32;
#pragma unroll
        for (int nt = 0; nt < NTL; nt++) {
            uint2 bf = bp[nt * 32];
            mma16816(acc[nt], qa, qb, qc, qd, bf.x, bf.y);
        }
    }

    // denominator = column 64 (n-tile 8, col offset 0), held by lanes with l%4==0
    float dlo = 1.f / __shfl_sync(~0u, acc[8][0], lane & ~3);
    float dhi = 1.f / __shfl_sync(~0u, acc[8][2], lane & ~3);
    float* o0 = out + (size_t)rlo * (NH * OD) + head * OD;
#pragma unroll
    for (int nt = 0; nt < 8; nt++) {
        int col = nt * 8 + c0;
        *(float2*)(o0 + col) = make_float2(acc[nt][0] * dlo, acc[nt][1] * dlo);
        *(float2*)(o0 + 8 * NH * OD + col) = make_float2(acc[nt][2] * dhi, acc[nt][3] * dhi);
    }
}

extern "C" void kernel_launch(void* const* d_in, const int* in_sizes, int n_in,
                              void* d_out, int out_size) {
    const float* x   = (const float*)d_in[0];
    const int*   adj = (const int*)d_in[1];
    const float* W   = (const float*)d_in[2];
    const float* att = (const float*)d_in[3];
    k_adjp<<<8192, 256>>>(adj);
    k_gemm_h<<<dim3(64, 4), 256>>>(x, W);
    k_etab<<<512, 256>>>(att);
    k_bfrag<<<1152, 256>>>();
    k_attn<<<128, 256>>>((float*)d_out);
}